// round 1
// baseline (speedup 1.0000x reference)
#include <cuda_runtime.h>

#define DM 64
#define MAXN 131072
#define MAXE 2097152
#define SCAN_BS 1024
#define MAXBLK 256   // MAXN / SCAN_BS = 128 <= 256

// ---------------- scratch (device globals; no allocation allowed) -----------
__device__ int   g_ecnt[MAXN];        // incoming-edge count (without self loop)
__device__ int   g_fill[MAXN];        // CSR fill cursors
__device__ int   g_rowptr[MAXN + 1];  // CSR row pointers (edges only)
__device__ int   g_bsum[MAXBLK];      // scan block sums
__device__ float g_dis[MAXN];         // deg^{-1/2} (deg includes self loop)
__device__ int   g_csrc[MAXE];        // CSR: source node per incoming edge
__device__ float g_gbuf[(size_t)MAXN * DM];  // g = (x@W) * dis[row]
__device__ float g_tbuf[(size_t)MAXN * DM];  // layer ping buffer

// ---------------- preprocessing kernels -------------------------------------
__global__ void k_init(int n) {
    int i = blockIdx.x * blockDim.x + threadIdx.x;
    if (i < n) { g_ecnt[i] = 0; g_fill[i] = 0; }
}

__global__ void k_count(const int* __restrict__ dst, int E) {
    int i = blockIdx.x * blockDim.x + threadIdx.x;
    if (i < E) atomicAdd(&g_ecnt[dst[i]], 1);
}

__global__ void k_dis(int n) {
    int i = blockIdx.x * blockDim.x + threadIdx.x;
    if (i < n) g_dis[i] = rsqrtf((float)(g_ecnt[i] + 1));  // +1 self loop
}

// scan pass 1: per-block sums of g_ecnt
__global__ void k_scan1(int n) {
    __shared__ int sh[SCAN_BS];
    int t = threadIdx.x;
    int i = blockIdx.x * SCAN_BS + t;
    sh[t] = (i < n) ? g_ecnt[i] : 0;
    __syncthreads();
    for (int s = SCAN_BS / 2; s > 0; s >>= 1) {
        if (t < s) sh[t] += sh[t + s];
        __syncthreads();
    }
    if (t == 0) g_bsum[blockIdx.x] = sh[0];
}

// scan pass 2: exclusive scan of block sums (single block)
__global__ void k_scan2(int nb) {
    __shared__ int sh[MAXBLK];
    int t = threadIdx.x;
    sh[t] = (t < nb) ? g_bsum[t] : 0;
    __syncthreads();
    for (int off = 1; off < MAXBLK; off <<= 1) {
        int v = (t >= off) ? sh[t - off] : 0;
        __syncthreads();
        sh[t] += v;
        __syncthreads();
    }
    g_bsum[t] = (t == 0) ? 0 : sh[t - 1];  // exclusive offsets
}

// scan pass 3: intra-block exclusive scan + block offset -> row_ptr
__global__ void k_scan3(int n) {
    __shared__ int sh[SCAN_BS];
    int t = threadIdx.x;
    int i = blockIdx.x * SCAN_BS + t;
    int v = (i < n) ? g_ecnt[i] : 0;
    sh[t] = v;
    __syncthreads();
    for (int off = 1; off < SCAN_BS; off <<= 1) {
        int u = (t >= off) ? sh[t - off] : 0;
        __syncthreads();
        sh[t] += u;
        __syncthreads();
    }
    int incl = sh[t];
    int base = g_bsum[blockIdx.x];
    if (i < n) {
        g_rowptr[i] = base + incl - v;
        if (i == n - 1) g_rowptr[n] = base + incl;
    }
}

__global__ void k_fill(const int* __restrict__ src, const int* __restrict__ dst, int E) {
    int e = blockIdx.x * blockDim.x + threadIdx.x;
    if (e < E) {
        int d = dst[e];
        int pos = g_rowptr[d] + atomicAdd(&g_fill[d], 1);
        g_csrc[pos] = src[e];
    }
}

// ---------------- GEMM: G[r][c] = (sum_k X[r][k]*W[k][c]) * dis[r] ----------
// 64x64 block tile, 256 threads (16x16), 4x4 micro tile per thread.
__global__ __launch_bounds__(256) void k_gemm(const float* __restrict__ X,
                                              const float* __restrict__ W,
                                              float* __restrict__ G, int n) {
    __shared__ float xs[64][72];  // 72 keeps float4 (16B) alignment per row
    __shared__ float ws[64][72];
    int tid  = threadIdx.x;
    int row0 = blockIdx.x * 64;

#pragma unroll
    for (int k = 0; k < 4; k++) {
        int idx = tid + k * 256;      // 1024 float4 slots
        int r = idx >> 4;
        int c = (idx & 15) << 2;
        float4 wv = *(const float4*)(W + r * DM + c);
        *(float4*)&ws[r][c] = wv;
        int gr = row0 + r;
        float4 xv = make_float4(0.f, 0.f, 0.f, 0.f);
        if (gr < n) xv = *(const float4*)(X + (size_t)gr * DM + c);
        *(float4*)&xs[r][c] = xv;
    }
    __syncthreads();

    int tx = tid & 15, ty = tid >> 4;
    float acc[4][4] = {};
#pragma unroll
    for (int k2 = 0; k2 < 64; k2++) {
        float a0 = xs[ty * 4 + 0][k2];
        float a1 = xs[ty * 4 + 1][k2];
        float a2 = xs[ty * 4 + 2][k2];
        float a3 = xs[ty * 4 + 3][k2];
        float4 wv = *(float4*)&ws[k2][tx * 4];
        acc[0][0] += a0 * wv.x; acc[0][1] += a0 * wv.y; acc[0][2] += a0 * wv.z; acc[0][3] += a0 * wv.w;
        acc[1][0] += a1 * wv.x; acc[1][1] += a1 * wv.y; acc[1][2] += a1 * wv.z; acc[1][3] += a1 * wv.w;
        acc[2][0] += a2 * wv.x; acc[2][1] += a2 * wv.y; acc[2][2] += a2 * wv.z; acc[2][3] += a2 * wv.w;
        acc[3][0] += a3 * wv.x; acc[3][1] += a3 * wv.y; acc[3][2] += a3 * wv.z; acc[3][3] += a3 * wv.w;
    }

#pragma unroll
    for (int i = 0; i < 4; i++) {
        int r = row0 + ty * 4 + i;
        if (r < n) {
            float s = g_dis[r];
            float4 o = make_float4(acc[i][0] * s, acc[i][1] * s, acc[i][2] * s, acc[i][3] * s);
            *(float4*)(G + (size_t)r * DM + tx * 4) = o;
        }
    }
}

// ---------------- aggregation: one warp per node -----------------------------
// out[i] = dis[i] * ( sum_{src in in(i)} g[src] + g[i] ) + b
__global__ __launch_bounds__(256) void k_agg(const float* __restrict__ G,
                                             const float* __restrict__ b,
                                             float* __restrict__ OUT, int n) {
    int w    = (blockIdx.x * blockDim.x + threadIdx.x) >> 5;
    int lane = threadIdx.x & 31;
    if (w >= n) return;

    int start = g_rowptr[w];
    int end   = g_rowptr[w + 1];

    const float2* G2 = (const float2*)G;
    float2 acc = G2[(size_t)w * 32 + lane];  // self-loop term (g[i])

    int p = start;
    // unroll by 2 for memory-level parallelism on the gathers
    for (; p + 1 < end; p += 2) {
        int s0 = g_csrc[p];
        int s1 = g_csrc[p + 1];
        float2 v0 = G2[(size_t)s0 * 32 + lane];
        float2 v1 = G2[(size_t)s1 * 32 + lane];
        acc.x += v0.x; acc.y += v0.y;
        acc.x += v1.x; acc.y += v1.y;
    }
    if (p < end) {
        int s0 = g_csrc[p];
        float2 v0 = G2[(size_t)s0 * 32 + lane];
        acc.x += v0.x; acc.y += v0.y;
    }

    float dv  = g_dis[w];
    float2 bb = ((const float2*)b)[lane];
    float2 o;
    o.x = dv * acc.x + bb.x;
    o.y = dv * acc.y + bb.y;
    ((float2*)OUT)[(size_t)w * 32 + lane] = o;
}

// ---------------- launch ------------------------------------------------------
extern "C" void kernel_launch(void* const* d_in, const int* in_sizes, int n_in,
                              void* d_out, int out_size) {
    const float* x  = (const float*)d_in[0];
    const int*   ei = (const int*)d_in[1];
    int n = in_sizes[0] / DM;
    int E = in_sizes[1] / 2;
    const int* src = ei;
    const int* dst = ei + E;

    const float* Wl[3] = { (const float*)d_in[2], (const float*)d_in[4], (const float*)d_in[6] };
    const float* bl[3] = { (const float*)d_in[3], (const float*)d_in[5], (const float*)d_in[7] };

    float* gbuf = nullptr;
    float* tbuf = nullptr;
    cudaGetSymbolAddress((void**)&gbuf, g_gbuf);
    cudaGetSymbolAddress((void**)&tbuf, g_tbuf);

    int nb = (n + SCAN_BS - 1) / SCAN_BS;

    // preprocessing (once; shared by all 3 layers)
    k_init <<<(n + 255) / 256, 256>>>(n);
    k_count<<<(E + 255) / 256, 256>>>(dst, E);
    k_dis  <<<(n + 255) / 256, 256>>>(n);
    k_scan1<<<nb, SCAN_BS>>>(n);
    k_scan2<<<1, MAXBLK>>>(nb);
    k_scan3<<<nb, SCAN_BS>>>(n);
    k_fill <<<(E + 255) / 256, 256>>>(src, dst, E);

    int gemm_blocks = (n + 63) / 64;
    int agg_blocks  = (n + 7) / 8;  // 8 warps per 256-thread block

    // layer 0: x -> tbuf
    k_gemm<<<gemm_blocks, 256>>>(x, Wl[0], gbuf, n);
    k_agg <<<agg_blocks, 256>>>(gbuf, bl[0], tbuf, n);
    // layer 1: tbuf -> tbuf
    k_gemm<<<gemm_blocks, 256>>>(tbuf, Wl[1], gbuf, n);
    k_agg <<<agg_blocks, 256>>>(gbuf, bl[1], tbuf, n);
    // layer 2: tbuf -> d_out
    k_gemm<<<gemm_blocks, 256>>>(tbuf, Wl[2], gbuf, n);
    k_agg <<<agg_blocks, 256>>>(gbuf, bl[2], (float*)d_out, n);
}